// round 6
// baseline (speedup 1.0000x reference)
#include <cuda_runtime.h>

// ---------------------------------------------------------------------------
// 2-layer LSTM decoder, persistent CTA = 32 batch rows, f32x2 FFMA GEMVs.
// Round-6: fused proj/sampler back in (free), layer1 depth-4 weight ring,
// layer2 W2/U2 interleaved (line-merged dual loads), ping-pong h (2 barriers).
// ---------------------------------------------------------------------------

#define ULL unsigned long long
#define T_STEPS 20
#define HP 36   // h row stride (floats), 16B-aligned
#define CP 33   // c row stride: conflict-free per-thread access

__device__ __forceinline__ ULL pack2(float x, float y) {
    ULL r; asm("mov.b64 %0, {%1, %2};" : "=l"(r) : "f"(x), "f"(y)); return r;
}
__device__ __forceinline__ float2 unpack2(ULL v) {
    float2 r; asm("mov.b64 {%0, %1}, %2;" : "=f"(r.x), "=f"(r.y) : "l"(v)); return r;
}
__device__ __forceinline__ ULL fma2(ULL a, ULL b, ULL c) {
    ULL d; asm("fma.rn.f32x2 %0, %1, %2, %3;" : "=l"(d) : "l"(a), "l"(b), "l"(c)); return d;
}
__device__ __forceinline__ float sigf(float x)  { return __fdividef(1.f, 1.f + __expf(-x)); }
__device__ __forceinline__ float tanhe(float x) { return __fdividef(2.f, 1.f + __expf(-2.f * x)) - 1.f; }

__device__ float4 g_w1q [64  * 256];             // W1 gate quads
__device__ float4 g_u1q [256 * 256 + 1024];      // U1 quads (+pad, depth-4 ring)
__device__ float4 g_wv2q[2 * (256 * 256 + 512)]; // interleaved {W2,U2} quads
__device__ float2 g_pw2 [256 * 80 + 80];         // (Wmu, Wlv) pairs [k][f]
__device__ float4 g_xw1q[8192 * 256];            // xw1 quads [row][u], bias folded

__global__ void repack_kernel(const float* __restrict__ W1, const float* __restrict__ U1,
                              const float* __restrict__ W2, const float* __restrict__ U2,
                              const float* __restrict__ Wmu, const float* __restrict__ Wlv) {
    int i = blockIdx.x * blockDim.x + threadIdx.x;   // 0..65535
    int k = i >> 8, u = i & 255;
    const float* r;
    if (i < 64 * 256) {
        r = W1 + k * 1024;
        g_w1q[i] = make_float4(r[u], r[256 + u], r[512 + u], r[768 + u]);
    }
    r = U1 + k * 1024;
    g_u1q[i] = make_float4(r[u], r[256 + u], r[512 + u], r[768 + u]);
    r = W2 + k * 1024;
    g_wv2q[2 * i]     = make_float4(r[u], r[256 + u], r[512 + u], r[768 + u]);
    r = U2 + k * 1024;
    g_wv2q[2 * i + 1] = make_float4(r[u], r[256 + u], r[512 + u], r[768 + u]);
    if (u < 80) g_pw2[k * 80 + u] = make_float2(Wmu[k * 80 + u], Wlv[k * 80 + u]);
}

__global__ void xw1_kernel(const float* __restrict__ z1, const float* __restrict__ z2,
                           const float* __restrict__ b1) {
    __shared__ float zt[8][64];
    const int tid = threadIdx.x;
    const int rb  = blockIdx.x * 8;
    for (int i = tid; i < 512; i += 256) {
        int r = i >> 6, k = i & 63;
        zt[r][k] = (k < 32) ? z1[(rb + r) * 32 + k] : z2[(rb + r) * 32 + (k - 32)];
    }
    __syncthreads();
    const int u = tid;
    float4 acc[8];
    #pragma unroll
    for (int r = 0; r < 8; r++) acc[r] = make_float4(0.f, 0.f, 0.f, 0.f);
    for (int k = 0; k < 64; k++) {
        float4 w = g_w1q[k * 256 + u];
        #pragma unroll
        for (int r = 0; r < 8; r++) {
            float zv = zt[r][k];
            acc[r].x += zv * w.x; acc[r].y += zv * w.y;
            acc[r].z += zv * w.z; acc[r].w += zv * w.w;
        }
    }
    float4 bq = make_float4(b1[u], b1[256 + u], b1[512 + u], b1[768 + u]);
    #pragma unroll
    for (int r = 0; r < 8; r++)
        g_xw1q[(size_t)(rb + r) * 256 + u] =
            make_float4(acc[r].x + bq.x, acc[r].y + bq.y, acc[r].z + bq.z, acc[r].w + bq.w);
}

// SMEM: h1[2][256][HP], h2[2][256][HP], c1/c2 [256][CP]
#define SMEM_FLOATS (4 * 256 * HP + 2 * 256 * CP)
#define SMEM_BYTES  (SMEM_FLOATS * 4)

__global__ void __launch_bounds__(512, 1) lstm_kernel(
    const float* __restrict__ b2, const float* __restrict__ bmu, const float* __restrict__ blv,
    const float* __restrict__ eps, float* __restrict__ out)
{
    extern __shared__ float sm[];
    float* h1b[2] = { sm,                sm + 256 * HP };
    float* h2b[2] = { sm + 2 * 256 * HP, sm + 3 * 256 * HP };
    float* c1s = sm + 4 * 256 * HP;
    float* c2s = c1s + 256 * CP;

    const int tid = threadIdx.x;
    const int u   = tid & 255;
    const int rg  = tid >> 8;
    const int r0  = rg * 16;
    const int rb  = blockIdx.x * 32;

    for (int i = tid; i < SMEM_FLOATS; i += 512) sm[i] = 0.f;
    __syncthreads();

    const ULL b2i = pack2(b2[u], b2[u]);
    const ULL b2f = pack2(b2[256 + u], b2[256 + u]);
    const ULL b2g = pack2(b2[512 + u], b2[512 + u]);
    const ULL b2o = pack2(b2[768 + u], b2[768 + u]);

    // fused proj+sampler mapping: 320 threads = 80 features x 4 row groups of 8
    const bool  pact = tid < 320;
    const int   pf   = pact ? (tid % 80) : 0;
    const int   pgp  = pact ? (tid / 80) : 0;
    const int   pr0  = pgp * 8;
    const float pbmu = pact ? bmu[pf] : 0.f;
    const float pblv = pact ? blv[pf] : 0.f;

    const float4* xq = g_xw1q + (size_t)(rb + r0) * 256 + u;

    ULL acc[4][8];
    int pp = 0;  // read h[pp], write h[pp^1]

    for (int t = 0; t < T_STEPS; t++) {
        // ================= layer 1: acc = xw1 + h1[pp] @ U1 =================
        #pragma unroll
        for (int p = 0; p < 8; p++) {
            float4 q0 = xq[(2 * p) * 256];
            float4 q1 = xq[(2 * p + 1) * 256];
            acc[0][p] = pack2(q0.x, q1.x);
            acc[1][p] = pack2(q0.y, q1.y);
            acc[2][p] = pack2(q0.z, q1.z);
            acc[3][p] = pack2(q0.w, q1.w);
        }
        {
            // depth-4 weight ring
            float4 w0 = g_u1q[u];
            float4 w1 = g_u1q[256 + u];
            float4 w2r = g_u1q[512 + u];
            float4 w3 = g_u1q[768 + u];
            const char* hb = (const char*)(h1b[pp] + r0);
            #pragma unroll 2
            for (int k = 0; k < 256; k++) {
                float4 wn = g_u1q[(k + 4) * 256 + u];
                ULL wi = pack2(w0.x, w0.x), wf = pack2(w0.y, w0.y);
                ULL wg = pack2(w0.z, w0.z), wo = pack2(w0.w, w0.w);
                const ulonglong2* hp = (const ulonglong2*)(hb + (size_t)k * (HP * 4));
                ulonglong2 a0 = hp[0], a1 = hp[1];
                #pragma unroll
                for (int p = 0; p < 4; p++) {
                    ULL hv = (p == 0) ? a0.x : (p == 1) ? a0.y : (p == 2) ? a1.x : a1.y;
                    acc[0][p] = fma2(hv, wi, acc[0][p]);
                    acc[1][p] = fma2(hv, wf, acc[1][p]);
                    acc[2][p] = fma2(hv, wg, acc[2][p]);
                    acc[3][p] = fma2(hv, wo, acc[3][p]);
                }
                ulonglong2 a2 = hp[2], a3 = hp[3];
                #pragma unroll
                for (int p = 4; p < 8; p++) {
                    ULL hv = (p == 4) ? a2.x : (p == 5) ? a2.y : (p == 6) ? a3.x : a3.y;
                    acc[0][p] = fma2(hv, wi, acc[0][p]);
                    acc[1][p] = fma2(hv, wf, acc[1][p]);
                    acc[2][p] = fma2(hv, wg, acc[2][p]);
                    acc[3][p] = fma2(hv, wo, acc[3][p]);
                }
                w0 = w1; w1 = w2r; w2r = w3; w3 = wn;
            }
        }
        // epilogue 1
        {
            float* h1n = h1b[pp ^ 1];
            #pragma unroll
            for (int p = 0; p < 8; p++) {
                float2 iv = unpack2(acc[0][p]);
                float2 fv = unpack2(acc[1][p]);
                float2 gv = unpack2(acc[2][p]);
                float2 ov = unpack2(acc[3][p]);
                int rr = r0 + 2 * p;
                float c0 = c1s[u * CP + rr], c1 = c1s[u * CP + rr + 1];
                c0 = sigf(fv.x) * c0 + sigf(iv.x) * tanhe(gv.x);
                c1 = sigf(fv.y) * c1 + sigf(iv.y) * tanhe(gv.y);
                c1s[u * CP + rr]     = c0;
                c1s[u * CP + rr + 1] = c1;
                *(float2*)(h1n + u * HP + rr) =
                    make_float2(sigf(ov.x) * tanhe(c0), sigf(ov.y) * tanhe(c1));
            }
        }
        __syncthreads();                       // (A) h1_new visible

        // ======== layer 2: acc = b2 + h1[pp^1] @ W2 + h2[pp] @ U2 ========
        #pragma unroll
        for (int p = 0; p < 8; p++) {
            acc[0][p] = b2i; acc[1][p] = b2f; acc[2][p] = b2g; acc[3][p] = b2o;
        }
        {
            const float4* wv = g_wv2q + 2 * u;
            float4 w0 = wv[0],        v0 = wv[1];
            float4 w1 = wv[2 * 256],  v1 = wv[2 * 256 + 1];
            const char* hb1 = (const char*)(h1b[pp ^ 1] + r0);
            const char* hb2 = (const char*)(h2b[pp] + r0);
            #pragma unroll 2
            for (int k = 0; k < 256; k++) {
                float4 wn = wv[2 * (k + 2) * 256];
                float4 vn = wv[2 * (k + 2) * 256 + 1];
                ULL wi = pack2(w0.x, w0.x), wf = pack2(w0.y, w0.y);
                ULL wg = pack2(w0.z, w0.z), wo = pack2(w0.w, w0.w);
                ULL vi = pack2(v0.x, v0.x), vf = pack2(v0.y, v0.y);
                ULL vg = pack2(v0.z, v0.z), vo = pack2(v0.w, v0.w);
                const ulonglong2* hp1 = (const ulonglong2*)(hb1 + (size_t)k * (HP * 4));
                const ulonglong2* hp2 = (const ulonglong2*)(hb2 + (size_t)k * (HP * 4));
                {
                    ulonglong2 a0 = hp1[0], a1 = hp1[1];
                    ulonglong2 b0 = hp2[0], b1v = hp2[1];
                    #pragma unroll
                    for (int p = 0; p < 4; p++) {
                        ULL h1v = (p == 0) ? a0.x : (p == 1) ? a0.y : (p == 2) ? a1.x : a1.y;
                        ULL h2v = (p == 0) ? b0.x : (p == 1) ? b0.y : (p == 2) ? b1v.x : b1v.y;
                        acc[0][p] = fma2(h1v, wi, acc[0][p]);
                        acc[1][p] = fma2(h1v, wf, acc[1][p]);
                        acc[2][p] = fma2(h1v, wg, acc[2][p]);
                        acc[3][p] = fma2(h1v, wo, acc[3][p]);
                        acc[0][p] = fma2(h2v, vi, acc[0][p]);
                        acc[1][p] = fma2(h2v, vf, acc[1][p]);
                        acc[2][p] = fma2(h2v, vg, acc[2][p]);
                        acc[3][p] = fma2(h2v, vo, acc[3][p]);
                    }
                }
                {
                    ulonglong2 a2 = hp1[2], a3 = hp1[3];
                    ulonglong2 b2v = hp2[2], b3 = hp2[3];
                    #pragma unroll
                    for (int p = 4; p < 8; p++) {
                        ULL h1v = (p == 4) ? a2.x : (p == 5) ? a2.y : (p == 6) ? a3.x : a3.y;
                        ULL h2v = (p == 4) ? b2v.x : (p == 5) ? b2v.y : (p == 6) ? b3.x : b3.y;
                        acc[0][p] = fma2(h1v, wi, acc[0][p]);
                        acc[1][p] = fma2(h1v, wf, acc[1][p]);
                        acc[2][p] = fma2(h1v, wg, acc[2][p]);
                        acc[3][p] = fma2(h1v, wo, acc[3][p]);
                        acc[0][p] = fma2(h2v, vi, acc[0][p]);
                        acc[1][p] = fma2(h2v, vf, acc[1][p]);
                        acc[2][p] = fma2(h2v, vg, acc[2][p]);
                        acc[3][p] = fma2(h2v, vo, acc[3][p]);
                    }
                }
                w0 = w1; w1 = wn; v0 = v1; v1 = vn;
            }
        }
        // epilogue 2
        {
            float* h2n = h2b[pp ^ 1];
            #pragma unroll
            for (int p = 0; p < 8; p++) {
                float2 iv = unpack2(acc[0][p]);
                float2 fv = unpack2(acc[1][p]);
                float2 gv = unpack2(acc[2][p]);
                float2 ov = unpack2(acc[3][p]);
                int rr = r0 + 2 * p;
                float c0 = c2s[u * CP + rr], c1 = c2s[u * CP + rr + 1];
                c0 = sigf(fv.x) * c0 + sigf(iv.x) * tanhe(gv.x);
                c1 = sigf(fv.y) * c1 + sigf(iv.y) * tanhe(gv.y);
                c2s[u * CP + rr]     = c0;
                c2s[u * CP + rr + 1] = c1;
                float2 hn = make_float2(sigf(ov.x) * tanhe(c0), sigf(ov.y) * tanhe(c1));
                *(float2*)(h2n + u * HP + rr) = hn;
                out[((size_t)(rb + rr) * T_STEPS + t) * 256 + u]     = hn.x;
                out[((size_t)(rb + rr + 1) * T_STEPS + t) * 256 + u] = hn.y;
            }
        }
        __syncthreads();                       // (B) h2_new visible

        // ---- fused mu/logvar projection + sampler (reads h2b[pp^1]) ----
        if (pact) {
            ULL amu[4], alv[4];
            #pragma unroll
            for (int q = 0; q < 4; q++) { amu[q] = 0ULL; alv[q] = 0ULL; }
            const char* hb = (const char*)(h2b[pp ^ 1] + pr0);
            float2 wv = g_pw2[pf];
            #pragma unroll 2
            for (int k = 0; k < 256; k++) {
                float2 wn = g_pw2[(k + 1) * 80 + pf];
                ULL wmu = pack2(wv.x, wv.x), wlv = pack2(wv.y, wv.y);
                const ulonglong2* hp = (const ulonglong2*)(hb + (size_t)k * (HP * 4));
                ulonglong2 h01 = hp[0], h23 = hp[1];
                #pragma unroll
                for (int q = 0; q < 4; q++) {
                    ULL hv = (q == 0) ? h01.x : (q == 1) ? h01.y : (q == 2) ? h23.x : h23.y;
                    amu[q] = fma2(hv, wmu, amu[q]);
                    alv[q] = fma2(hv, wlv, alv[q]);
                }
                wv = wn;
            }
            #pragma unroll
            for (int q = 0; q < 4; q++) {
                float2 mu = unpack2(amu[q]);
                float2 lv = unpack2(alv[q]);
                mu.x += pbmu; mu.y += pbmu;
                lv.x += pblv; lv.y += pblv;
                int r = pr0 + 2 * q;
                size_t b0 = ((size_t)(rb + r)     * T_STEPS + t) * 80 + pf;
                size_t b1 = ((size_t)(rb + r + 1) * T_STEPS + t) * 80 + pf;
                float e0 = eps[b0], e1 = eps[b1];
                out[41943040u + b0] = mu.x;
                out[41943040u + b1] = mu.y;
                out[55050240u + b0] = lv.x;
                out[55050240u + b1] = lv.y;
                out[68157440u + b0] = e0 * __expf(0.5f * mu.x) + lv.x;
                out[68157440u + b1] = e1 * __expf(0.5f * mu.y) + lv.y;
            }
        }
        // no extra barrier: next writes touch other ping-pong buffers,
        // and are ordered behind barriers (A)/(B) of step t+1.
        pp ^= 1;
    }
}

extern "C" void kernel_launch(void* const* d_in, const int* in_sizes, int n_in,
                              void* d_out, int out_size) {
    // order: x, z1, z2, eps, W1, U1, b1, W2, U2, b2, Wmu, bmu, Wlv, blv
    const float* z1  = (const float*)d_in[1];
    const float* z2  = (const float*)d_in[2];
    const float* eps = (const float*)d_in[3];
    const float* W1  = (const float*)d_in[4];
    const float* U1  = (const float*)d_in[5];
    const float* b1  = (const float*)d_in[6];
    const float* W2  = (const float*)d_in[7];
    const float* U2  = (const float*)d_in[8];
    const float* b2  = (const float*)d_in[9];
    const float* Wmu = (const float*)d_in[10];
    const float* bmu = (const float*)d_in[11];
    const float* Wlv = (const float*)d_in[12];
    const float* blv = (const float*)d_in[13];
    float* out = (float*)d_out;

    cudaFuncSetAttribute(lstm_kernel, cudaFuncAttributeMaxDynamicSharedMemorySize, SMEM_BYTES);

    repack_kernel<<<256, 256>>>(W1, U1, W2, U2, Wmu, Wlv);
    xw1_kernel<<<1024, 256>>>(z1, z2, b1);
    lstm_kernel<<<256, 512, SMEM_BYTES>>>(b2, bmu, blv, eps, out);
}